// round 2
// baseline (speedup 1.0000x reference)
#include <cuda_runtime.h>
#include <math.h>

#define BB 2
#define II 768
#define CA 768
#define CS 384
#define CZ 128
#define HH 16
#define DD 48
#define HC 768
#define QS 3072             /* packed qkvg row stride */
#define MM (BB*II)          /* 1536 rows */
#define EPSV 1e-5f

/* ---------------- scratch (no allocations allowed) ---------------- */
__device__ float g_aln[MM * CA];
__device__ float g_sln[MM * CS];
__device__ float g_a[MM * CA];
__device__ float g_Wqkvg[CA * QS];                      /* packed Wq|Wk|Wv|Wg */
__device__ float g_qkvg[MM * QS];                       /* packed q|k|v|g    */
__device__ float g_gate2[MM * CA];
__device__ float g_o[MM * HC];
__device__ float g_scores[(size_t)BB * HH * II * II];   /* [b,h,i,j] 75.5 MB */

/* ---------------- weight packing: [768][768]x4 -> [768][3072] ------------ */
__global__ __launch_bounds__(256) void pack_w(const float* __restrict__ Wq,
                                              const float* __restrict__ Wk,
                                              const float* __restrict__ Wv,
                                              const float* __restrict__ Wg,
                                              float* __restrict__ P)
{
    int idx = blockIdx.x * 256 + threadIdx.x;       /* over CA*HC/4 float4s */
    int r = idx / (HC / 4), c4 = idx % (HC / 4);
    float4 q4 = ((const float4*)Wq)[idx];
    float4 k4 = ((const float4*)Wk)[idx];
    float4 v4 = ((const float4*)Wv)[idx];
    float4 g4 = ((const float4*)Wg)[idx];
    float4* row = (float4*)(P + (size_t)r * QS);
    row[c4]                 = q4;
    row[c4 + HC / 4]        = k4;
    row[c4 + 2 * (HC / 4)]  = v4;
    row[c4 + 3 * (HC / 4)]  = g4;
}

/* ---------------- LayerNorm (block per row) ---------------- */
template<int W, bool AFFINE>
__global__ __launch_bounds__(256) void ln_kernel(const float* __restrict__ x,
                                                 const float* __restrict__ w,
                                                 const float* __restrict__ bvec,
                                                 float* __restrict__ y)
{
    int row = blockIdx.x;
    const float* xr = x + (size_t)row * W;
    float* yr = y + (size_t)row * W;
    float vals[(W + 255) / 256];
    float s = 0.f, ss = 0.f;
    int cnt = 0;
    for (int c = threadIdx.x; c < W; c += 256) {
        float v = xr[c];
        vals[cnt++] = v;
        s += v; ss += v * v;
    }
    __shared__ float sh1[8], sh2[8];
    int lane = threadIdx.x & 31, wid = threadIdx.x >> 5;
#pragma unroll
    for (int off = 16; off; off >>= 1) {
        s  += __shfl_xor_sync(0xffffffffu, s,  off);
        ss += __shfl_xor_sync(0xffffffffu, ss, off);
    }
    if (lane == 0) { sh1[wid] = s; sh2[wid] = ss; }
    __syncthreads();
    if (threadIdx.x == 0) {
        float ts = 0.f, tss = 0.f;
        for (int q = 0; q < 8; q++) { ts += sh1[q]; tss += sh2[q]; }
        sh1[0] = ts; sh2[0] = tss;
    }
    __syncthreads();
    s = sh1[0]; ss = sh2[0];
    float mean = s * (1.0f / W);
    float var  = ss * (1.0f / W) - mean * mean;
    float inv  = rsqrtf(var + EPSV);
    cnt = 0;
    for (int c = threadIdx.x; c < W; c += 256) {
        float v = (vals[cnt++] - mean) * inv;
        if (AFFINE) v = v * w[c] + bvec[c];
        yr[c] = v;
    }
}

/* ---------------- 128x64 tile fp32 GEMM, 8x4 micro-tile ----------------
   EPI: 3 sigmoid(+bias[n]) | 4 *extra[m,n] | 5 qkvg-segment epilogue */
template<int EPI>
__global__ __launch_bounds__(256) void gemm128(const float* __restrict__ A,
                                               const float* __restrict__ Bm,
                                               float* __restrict__ C,
                                               const float* __restrict__ bias,
                                               const float* __restrict__ extra,
                                               int M, int N, int K)
{
    __shared__ float As[16][132];
    __shared__ float Bs[16][64];
    int m0 = blockIdx.y * 128, n0 = blockIdx.x * 64;
    int tid = threadIdx.x, tx = tid & 15, ty = tid >> 4;
    int arow = tid >> 2, acol = (tid & 3) * 4;
    int bk = tid >> 4, bn = (tid & 15) * 4;
    float acc[8][4] = {};
    for (int k0 = 0; k0 < K; k0 += 16) {
#pragma unroll
        for (int r = 0; r < 2; r++) {
            float4 av = *(const float4*)&A[(size_t)(m0 + arow + r * 64) * K + k0 + acol];
            As[acol + 0][arow + r * 64] = av.x;
            As[acol + 1][arow + r * 64] = av.y;
            As[acol + 2][arow + r * 64] = av.z;
            As[acol + 3][arow + r * 64] = av.w;
        }
        *(float4*)&Bs[bk][bn] = *(const float4*)&Bm[(size_t)(k0 + bk) * N + n0 + bn];
        __syncthreads();
#pragma unroll
        for (int k = 0; k < 16; k++) {
            float4 a0 = *(const float4*)&As[k][ty * 8];
            float4 a1 = *(const float4*)&As[k][ty * 8 + 4];
            float4 b4 = *(const float4*)&Bs[k][tx * 4];
            float av[8] = {a0.x, a0.y, a0.z, a0.w, a1.x, a1.y, a1.z, a1.w};
            float bv[4] = {b4.x, b4.y, b4.z, b4.w};
#pragma unroll
            for (int i2 = 0; i2 < 8; i2++)
#pragma unroll
                for (int j2 = 0; j2 < 4; j2++)
                    acc[i2][j2] += av[i2] * bv[j2];
        }
        __syncthreads();
    }
#pragma unroll
    for (int i2 = 0; i2 < 8; i2++) {
        int m = m0 + ty * 8 + i2;
#pragma unroll
        for (int j2 = 0; j2 < 4; j2++) {
            int n = n0 + tx * 4 + j2;
            float v = acc[i2][j2];
            if (EPI == 3) { v += bias[n]; v = 1.f / (1.f + __expf(-v)); }
            else if (EPI == 4) v *= extra[(size_t)m * N + n];
            else if (EPI == 5) {
                if (n < HC) v += bias[n];                     /* q: +bq    */
                else if (n >= 3 * HC) v = 1.f / (1.f + __expf(-v)); /* g */
            }
            C[(size_t)m * N + n] = v;
        }
    }
}

/* ---------------- adaln fused dual GEMM (64x64):
   C = sigmoid(A@B1 + bias) * aln + A@B2    (M=1536, N=768, K=384) */
__global__ __launch_bounds__(256) void adaln_gemm(const float* __restrict__ A,
                                                  const float* __restrict__ B1,
                                                  const float* __restrict__ B2,
                                                  const float* __restrict__ bias,
                                                  const float* __restrict__ aln,
                                                  float* __restrict__ C)
{
    const int N = CA, K = CS;
    __shared__ float As[16][68];
    __shared__ float Bs1[16][64];
    __shared__ float Bs2[16][64];
    int m0 = blockIdx.y * 64, n0 = blockIdx.x * 64;
    int tid = threadIdx.x, tx = tid & 15, ty = tid >> 4;
    float acc1[4][4] = {}, acc2[4][4] = {};
    for (int k0 = 0; k0 < K; k0 += 16) {
        int kk = tid & 15, mb = tid >> 4;
#pragma unroll
        for (int r = 0; r < 4; r++)
            As[kk][mb + r * 16] = A[(size_t)(m0 + mb + r * 16) * K + k0 + kk];
        int nn = tid & 63, kb = tid >> 6;
#pragma unroll
        for (int r = 0; r < 4; r++) {
            Bs1[kb + r * 4][nn] = B1[(size_t)(k0 + kb + r * 4) * N + n0 + nn];
            Bs2[kb + r * 4][nn] = B2[(size_t)(k0 + kb + r * 4) * N + n0 + nn];
        }
        __syncthreads();
#pragma unroll
        for (int k = 0; k < 16; k++) {
            float4 a4 = *(const float4*)&As[k][ty * 4];
            float4 c4 = *(const float4*)&Bs1[k][tx * 4];
            float4 d4 = *(const float4*)&Bs2[k][tx * 4];
            float av[4] = {a4.x, a4.y, a4.z, a4.w};
            float b1v[4] = {c4.x, c4.y, c4.z, c4.w};
            float b2v[4] = {d4.x, d4.y, d4.z, d4.w};
#pragma unroll
            for (int i2 = 0; i2 < 4; i2++)
#pragma unroll
                for (int j2 = 0; j2 < 4; j2++) {
                    acc1[i2][j2] += av[i2] * b1v[j2];
                    acc2[i2][j2] += av[i2] * b2v[j2];
                }
        }
        __syncthreads();
    }
#pragma unroll
    for (int i2 = 0; i2 < 4; i2++) {
        int m = m0 + ty * 4 + i2;
#pragma unroll
        for (int j2 = 0; j2 < 4; j2++) {
            int n = n0 + tx * 4 + j2;
            float gsig = 1.f / (1.f + __expf(-(acc1[i2][j2] + bias[n])));
            C[(size_t)m * N + n] = gsig * aln[(size_t)m * N + n] + acc2[i2][j2];
        }
    }
}

/* ---------------- pair bias: LN(z,128) @ Wb + beta -> scores[b,h,i,j] ----
   block = 1024 thr = 32 warps; warp w handles j = jt*32+w for fixed (b,i). */
__global__ __launch_bounds__(1024) void pairbias_kernel(const float* __restrict__ z,
                                                        const float* __restrict__ beta,
                                                        const float* __restrict__ lnw,
                                                        const float* __restrict__ lnb,
                                                        const float* __restrict__ Wb,
                                                        float* __restrict__ S)
{
    __shared__ float sWbT[16][128];
    __shared__ float sw[128], sb[128];
    __shared__ float sbeta[512];
    __shared__ float stage[16][32];
    int b = blockIdx.z, i = blockIdx.y, jt = blockIdx.x;
    int tid = threadIdx.x;
    for (int idx = tid; idx < 2048; idx += 1024) {
        int c = idx >> 4, h = idx & 15;           /* Wb row-major [128][16] */
        sWbT[h][c] = Wb[idx];
    }
    if (tid < 128) { sw[tid] = lnw[tid]; sb[tid] = lnb[tid]; }
    if (tid < 512) {
        size_t bo = ((size_t)(b * II + i) * II + jt * 32) * HH;
        sbeta[tid] = beta[bo + tid];              /* [j within tile][h], coalesced */
    }
    __syncthreads();
    int w = tid >> 5, lane = tid & 31;
    int j = jt * 32 + w;
    const float4 z4 = *(const float4*)(z + ((size_t)(b * II + i) * II + j) * CZ + lane * 4);
    float s  = z4.x + z4.y + z4.z + z4.w;
    float ss = z4.x * z4.x + z4.y * z4.y + z4.z * z4.z + z4.w * z4.w;
#pragma unroll
    for (int off = 16; off; off >>= 1) {
        s  += __shfl_xor_sync(0xffffffffu, s,  off);
        ss += __shfl_xor_sync(0xffffffffu, ss, off);
    }
    float mean = s * (1.f / CZ);
    float var  = ss * (1.f / CZ) - mean * mean;
    float inv  = rsqrtf(var + EPSV);
    int c0 = lane * 4;
    float y0 = (z4.x - mean) * inv * sw[c0 + 0] + sb[c0 + 0];
    float y1 = (z4.y - mean) * inv * sw[c0 + 1] + sb[c0 + 1];
    float y2 = (z4.z - mean) * inv * sw[c0 + 2] + sb[c0 + 2];
    float y3 = (z4.w - mean) * inv * sw[c0 + 3] + sb[c0 + 3];
    float acc[16];
#pragma unroll
    for (int h = 0; h < 16; h++) {
        float4 wv = *(const float4*)&sWbT[h][c0];
        acc[h] = y0 * wv.x + y1 * wv.y + y2 * wv.z + y3 * wv.w;
    }
#pragma unroll
    for (int off = 16; off; off >>= 1)
#pragma unroll
        for (int h = 0; h < 16; h++)
            acc[h] += __shfl_xor_sync(0xffffffffu, acc[h], off);
    if (lane < 16) stage[lane][w] = acc[lane];
    __syncthreads();
    if (tid < 512) {                              /* coalesced j-contiguous write */
        int h = tid >> 5, jj = tid & 31;
        S[((size_t)(b * HH + h) * II + i) * II + jt * 32 + jj] =
            stage[h][jj] + sbeta[jj * HH + h];
    }
}

/* ---------------- QK^T (K=48 single tile), accumulate into scores ------- */
__global__ __launch_bounds__(256) void qk_kernel(const float* __restrict__ Q,
                                                 const float* __restrict__ Kmat,
                                                 float* __restrict__ S)
{
    int bh = blockIdx.z;
    int b = bh >> 4, h = bh & 15;
    int i0 = blockIdx.y * 64, j0 = blockIdx.x * 64;
    __shared__ float Qs[DD][68];
    __shared__ float Ks[DD][68];
    int tid = threadIdx.x, tx = tid & 15, ty = tid >> 4;
#pragma unroll
    for (int e = 0; e < 12; e++) {
        int idx = tid + e * 256;
        int row = idx / DD, d = idx % DD;
        Qs[d][row] = Q[(size_t)(b * II + i0 + row) * QS + h * DD + d];
        Ks[d][row] = Kmat[(size_t)(b * II + j0 + row) * QS + h * DD + d];
    }
    __syncthreads();
    float acc[4][4] = {};
#pragma unroll
    for (int d = 0; d < DD; d++) {
        float4 a4 = *(const float4*)&Qs[d][ty * 4];
        float4 b4 = *(const float4*)&Ks[d][tx * 4];
        float av[4] = {a4.x, a4.y, a4.z, a4.w};
        float bv[4] = {b4.x, b4.y, b4.z, b4.w};
#pragma unroll
        for (int i2 = 0; i2 < 4; i2++)
#pragma unroll
            for (int j2 = 0; j2 < 4; j2++)
                acc[i2][j2] += av[i2] * bv[j2];
    }
    const float scale = 0.14433756729740643f;     /* 1/sqrt(48) */
#pragma unroll
    for (int i2 = 0; i2 < 4; i2++) {
        int ii = i0 + ty * 4 + i2;
        float4* sp = (float4*)&S[((size_t)bh * II + ii) * II + j0 + tx * 4];
        float4 ov = *sp;
        ov.x += acc[i2][0] * scale;
        ov.y += acc[i2][1] * scale;
        ov.z += acc[i2][2] * scale;
        ov.w += acc[i2][3] * scale;
        *sp = ov;
    }
}

/* ---------------- softmax over j (row = b,h,i) ---------------- */
__global__ __launch_bounds__(256) void softmax_kernel(float* __restrict__ S)
{
    float* p = S + (size_t)blockIdx.x * II;
    int tid = threadIdx.x;
    float a0 = p[tid], a1 = p[tid + 256], a2 = p[tid + 512];
    float m = fmaxf(a0, fmaxf(a1, a2));
    __shared__ float sh[8];
    int lane = tid & 31, wid = tid >> 5;
#pragma unroll
    for (int off = 16; off; off >>= 1)
        m = fmaxf(m, __shfl_xor_sync(0xffffffffu, m, off));
    if (lane == 0) sh[wid] = m;
    __syncthreads();
    if (tid == 0) {
        float t = sh[0];
        for (int q = 1; q < 8; q++) t = fmaxf(t, sh[q]);
        sh[0] = t;
    }
    __syncthreads();
    m = sh[0];
    float e0 = __expf(a0 - m), e1 = __expf(a1 - m), e2 = __expf(a2 - m);
    float s = e0 + e1 + e2;
    __syncthreads();
#pragma unroll
    for (int off = 16; off; off >>= 1)
        s += __shfl_xor_sync(0xffffffffu, s, off);
    if (lane == 0) sh[wid] = s;
    __syncthreads();
    if (tid == 0) {
        float t = 0.f;
        for (int q = 0; q < 8; q++) t += sh[q];
        sh[0] = t;
    }
    __syncthreads();
    float inv = 1.f / sh[0];
    p[tid] = e0 * inv; p[tid + 256] = e1 * inv; p[tid + 512] = e2 * inv;
}

/* ---------------- A@V with fused gating: o = (A@V)*g ---------------- */
__global__ __launch_bounds__(256) void av_kernel(const float* __restrict__ S,
                                                 const float* __restrict__ V,
                                                 const float* __restrict__ G,
                                                 float* __restrict__ O)
{
    int bh = blockIdx.y;
    int b = bh >> 4, h = bh & 15;
    int i0 = blockIdx.x * 64;
    __shared__ float SsT[64][68];   /* [j][i] */
    __shared__ float Vs[64][48];    /* [j][d] */
    int tid = threadIdx.x, tx = tid & 15, ty = tid >> 4;
    float acc[4][3] = {};
    for (int j0 = 0; j0 < II; j0 += 64) {
        int col = tid & 63, rb = tid >> 6;
#pragma unroll
        for (int r = 0; r < 16; r++) {
            int row = rb + r * 4;
            SsT[col][row] = S[((size_t)bh * II + i0 + row) * II + j0 + col];
        }
#pragma unroll
        for (int e = 0; e < 12; e++) {
            int idx = tid + e * 256;
            int row = idx / DD, d = idx % DD;
            Vs[row][d] = V[(size_t)(b * II + j0 + row) * QS + h * DD + d];
        }
        __syncthreads();
#pragma unroll
        for (int jk = 0; jk < 64; jk++) {
            float4 a4 = *(const float4*)&SsT[jk][ty * 4];
            float av4[4] = {a4.x, a4.y, a4.z, a4.w};
            float v0 = Vs[jk][tx * 3 + 0];
            float v1 = Vs[jk][tx * 3 + 1];
            float v2 = Vs[jk][tx * 3 + 2];
#pragma unroll
            for (int i2 = 0; i2 < 4; i2++) {
                acc[i2][0] += av4[i2] * v0;
                acc[i2][1] += av4[i2] * v1;
                acc[i2][2] += av4[i2] * v2;
            }
        }
        __syncthreads();
    }
#pragma unroll
    for (int i2 = 0; i2 < 4; i2++) {
        int ii = i0 + ty * 4 + i2;
#pragma unroll
        for (int t = 0; t < 3; t++) {
            int d = tx * 3 + t;
            size_t gidx = (size_t)(b * II + ii) * QS + h * DD + d;     /* G in packed buf */
            size_t oidx = (size_t)(b * II + ii) * HC + h * DD + d;     /* O compact      */
            O[oidx] = acc[i2][t] * G[gidx];
        }
    }
}

/* ---------------- host launcher ---------------- */
extern "C" void kernel_launch(void* const* d_in, const int* in_sizes, int n_in,
                              void* d_out, int out_size)
{
    (void)in_sizes; (void)n_in; (void)out_size;
    const float* a_i  = (const float*)d_in[0];
    const float* s_i  = (const float*)d_in[1];
    const float* z_ij = (const float*)d_in[2];
    const float* beta = (const float*)d_in[3];
    const float* lnsw = (const float*)d_in[4];
    const float* lnsb = (const float*)d_in[5];
    const float* Ws   = (const float*)d_in[6];
    const float* bs   = (const float*)d_in[7];
    const float* Wnb  = (const float*)d_in[8];
    const float* Wq   = (const float*)d_in[9];
    const float* bq   = (const float*)d_in[10];
    const float* Wk   = (const float*)d_in[11];
    const float* Wv   = (const float*)d_in[12];
    const float* lnbw = (const float*)d_in[13];
    const float* lnbb = (const float*)d_in[14];
    const float* Wb   = (const float*)d_in[15];
    const float* Wg   = (const float*)d_in[16];
    const float* Wo   = (const float*)d_in[17];
    const float* Wso  = (const float*)d_in[18];
    const float* bso  = (const float*)d_in[19];
    float* out = (float*)d_out;

    float *aln, *sln, *a, *wpk, *qkvg, *gate2, *o, *scores;
    cudaGetSymbolAddress((void**)&aln,    g_aln);
    cudaGetSymbolAddress((void**)&sln,    g_sln);
    cudaGetSymbolAddress((void**)&a,      g_a);
    cudaGetSymbolAddress((void**)&wpk,    g_Wqkvg);
    cudaGetSymbolAddress((void**)&qkvg,   g_qkvg);
    cudaGetSymbolAddress((void**)&gate2,  g_gate2);
    cudaGetSymbolAddress((void**)&o,      g_o);
    cudaGetSymbolAddress((void**)&scores, g_scores);

    /* weight packing (overlappable with LN) */
    pack_w<<<(CA * HC / 4) / 256, 256>>>(Wq, Wk, Wv, Wg, wpk);

    /* LayerNorms */
    ln_kernel<CA, false><<<MM, 256>>>(a_i, nullptr, nullptr, aln);
    ln_kernel<CS, true ><<<MM, 256>>>(s_i, lnsw, lnsb, sln);

    /* adaln: a = sigmoid(sln@Ws + bs) * aln + sln@Wnb */
    adaln_gemm<<<dim3(CA / 64, MM / 64), 256>>>(sln, Ws, Wnb, bs, aln, a);

    /* fused q|k|v|g projection GEMM: [1536,768] @ [768,3072] */
    gemm128<5><<<dim3(QS / 64, MM / 128), 256>>>(a, wpk, qkvg, bq, nullptr, MM, QS, CA);

    /* output gate from RAW s_i: sigmoid(s_i@Ws_out + bs_out) */
    gemm128<3><<<dim3(CA / 64, MM / 128), 256>>>(s_i, Wso, gate2, bso, nullptr, MM, CA, CS);

    /* pair bias -> scores[b,h,i,j] */
    pairbias_kernel<<<dim3(II / 32, II, BB), 1024>>>(z_ij, beta, lnbw, lnbb, Wb, scores);

    /* scores += q.k / sqrt(d); softmax over j; o = (A@V)*g */
    qk_kernel<<<dim3(II / 64, II / 64, BB * HH), 256>>>(qkvg, qkvg + HC, scores);
    softmax_kernel<<<BB * HH * II, 256>>>(scores);
    av_kernel<<<dim3(II / 64, BB * HH), 256>>>(scores, qkvg + 2 * HC, qkvg + 3 * HC, o);

    /* out = gate2 * (o @ Wo) */
    gemm128<4><<<dim3(CA / 64, MM / 128), 256>>>(o, Wo, out, nullptr, gate2, MM, CA, HC);
}

// round 3
// speedup vs baseline: 1.1694x; 1.1694x over previous
#include <cuda_runtime.h>
#include <math.h>

#define BB 2
#define II 768
#define CA 768
#define CS 384
#define CZ 128
#define HH 16
#define DD 48
#define HC 768
#define QS 3072             /* packed qkvg row stride */
#define MM (BB*II)          /* 1536 rows */
#define EPSV 1e-5f

/* ---------------- scratch (no allocations allowed) ---------------- */
__device__ float g_aln[MM * CA];
__device__ float g_sln[MM * CS];
__device__ float g_a[MM * CA];
__device__ float g_Wqkvg[CA * QS];                      /* packed Wq|Wk|Wv|Wg */
__device__ float g_qkvg[MM * QS];                       /* packed q|k|v|g    */
__device__ float g_gate2[MM * CA];
__device__ float g_o[MM * HC];
__device__ float g_bias[(size_t)BB * HH * II * II];     /* [b,h,i,j] 75.5 MB */

/* ---------------- weight packing: [768][768]x4 -> [768][3072] ------------ */
__global__ __launch_bounds__(256) void pack_w(const float* __restrict__ Wq,
                                              const float* __restrict__ Wk,
                                              const float* __restrict__ Wv,
                                              const float* __restrict__ Wg,
                                              float* __restrict__ P)
{
    int idx = blockIdx.x * 256 + threadIdx.x;       /* over CA*HC/4 float4s */
    int r = idx / (HC / 4), c4 = idx % (HC / 4);
    float4 q4 = ((const float4*)Wq)[idx];
    float4 k4 = ((const float4*)Wk)[idx];
    float4 v4 = ((const float4*)Wv)[idx];
    float4 g4 = ((const float4*)Wg)[idx];
    float4* row = (float4*)(P + (size_t)r * QS);
    row[c4]                 = q4;
    row[c4 + HC / 4]        = k4;
    row[c4 + 2 * (HC / 4)]  = v4;
    row[c4 + 3 * (HC / 4)]  = g4;
}

/* ---------------- LayerNorm (block per row) ---------------- */
template<int W, bool AFFINE>
__global__ __launch_bounds__(256) void ln_kernel(const float* __restrict__ x,
                                                 const float* __restrict__ w,
                                                 const float* __restrict__ bvec,
                                                 float* __restrict__ y)
{
    int row = blockIdx.x;
    const float* xr = x + (size_t)row * W;
    float* yr = y + (size_t)row * W;
    float vals[(W + 255) / 256];
    float s = 0.f, ss = 0.f;
    int cnt = 0;
    for (int c = threadIdx.x; c < W; c += 256) {
        float v = xr[c];
        vals[cnt++] = v;
        s += v; ss += v * v;
    }
    __shared__ float sh1[8], sh2[8];
    int lane = threadIdx.x & 31, wid = threadIdx.x >> 5;
#pragma unroll
    for (int off = 16; off; off >>= 1) {
        s  += __shfl_xor_sync(0xffffffffu, s,  off);
        ss += __shfl_xor_sync(0xffffffffu, ss, off);
    }
    if (lane == 0) { sh1[wid] = s; sh2[wid] = ss; }
    __syncthreads();
    if (threadIdx.x == 0) {
        float ts = 0.f, tss = 0.f;
        for (int q = 0; q < 8; q++) { ts += sh1[q]; tss += sh2[q]; }
        sh1[0] = ts; sh2[0] = tss;
    }
    __syncthreads();
    s = sh1[0]; ss = sh2[0];
    float mean = s * (1.0f / W);
    float var  = ss * (1.0f / W) - mean * mean;
    float inv  = rsqrtf(var + EPSV);
    cnt = 0;
    for (int c = threadIdx.x; c < W; c += 256) {
        float v = (vals[cnt++] - mean) * inv;
        if (AFFINE) v = v * w[c] + bvec[c];
        yr[c] = v;
    }
}

/* ---------------- 128x128 tile fp32 GEMM, 8x8 micro-tile ----------------
   Balanced: 64B LDS per 64 FMA per thread per k.
   n-mapping per thread: cols {tx*4..+3} and {64+tx*4..+3} (conflict-free LDS.128)
   EPI: 3 sigmoid(A@B+bias) | 4 (A@B)*extra | 5 qkvg segments */
template<int EPI>
__global__ __launch_bounds__(256) void gemm_big(const float* __restrict__ A,
                                                const float* __restrict__ Bm,
                                                float* __restrict__ C,
                                                const float* __restrict__ bias,
                                                const float* __restrict__ extra,
                                                int M, int N, int K)
{
    __shared__ float As[16][132];
    __shared__ float Bs[16][132];
    int m0 = blockIdx.y * 128, n0 = blockIdx.x * 128;
    int tid = threadIdx.x, tx = tid & 15, ty = tid >> 4;
    int akk = tid & 15, amr = tid >> 4;           /* A: col k, base row */
    int bkr = tid >> 5, bcn = (tid & 31) * 4;     /* B: base k-row, col */
    float acc[8][8] = {};
    for (int k0 = 0; k0 < K; k0 += 16) {
#pragma unroll
        for (int r = 0; r < 8; r++)
            As[akk][amr + 16 * r] = A[(size_t)(m0 + amr + 16 * r) * K + k0 + akk];
#pragma unroll
        for (int r = 0; r < 2; r++) {
            int br = bkr + 8 * r;
            *(float4*)&Bs[br][bcn] = *(const float4*)&Bm[(size_t)(k0 + br) * N + n0 + bcn];
        }
        __syncthreads();
#pragma unroll
        for (int k = 0; k < 16; k++) {
            float4 a0 = *(const float4*)&As[k][ty * 8];
            float4 a1 = *(const float4*)&As[k][ty * 8 + 4];
            float4 b0 = *(const float4*)&Bs[k][tx * 4];
            float4 b1 = *(const float4*)&Bs[k][64 + tx * 4];
            float av[8] = {a0.x, a0.y, a0.z, a0.w, a1.x, a1.y, a1.z, a1.w};
            float bv[8] = {b0.x, b0.y, b0.z, b0.w, b1.x, b1.y, b1.z, b1.w};
#pragma unroll
            for (int i2 = 0; i2 < 8; i2++)
#pragma unroll
                for (int j2 = 0; j2 < 8; j2++)
                    acc[i2][j2] += av[i2] * bv[j2];
        }
        __syncthreads();
    }
#pragma unroll
    for (int i2 = 0; i2 < 8; i2++) {
        int m = m0 + ty * 8 + i2;
#pragma unroll
        for (int half = 0; half < 2; half++) {
            int nb = n0 + half * 64 + tx * 4;
            float4 v;
            float* vp = &v.x;
#pragma unroll
            for (int j2 = 0; j2 < 4; j2++) {
                int n = nb + j2;
                float val = acc[i2][half * 4 + j2];
                if (EPI == 3) { val += bias[n]; val = 1.f / (1.f + __expf(-val)); }
                else if (EPI == 4) val *= extra[(size_t)m * N + n];
                else if (EPI == 5) {
                    if (n < HC) val += bias[n];                          /* q: +bq */
                    else if (n >= 3 * HC) val = 1.f / (1.f + __expf(-val)); /* g */
                }
                vp[j2] = val;
            }
            *(float4*)&C[(size_t)m * N + nb] = v;
        }
    }
}

/* ---------------- adaln fused dual GEMM (64x64):
   C = sigmoid(A@B1 + bias) * aln + A@B2    (M=1536, N=768, K=384) */
__global__ __launch_bounds__(256) void adaln_gemm(const float* __restrict__ A,
                                                  const float* __restrict__ B1,
                                                  const float* __restrict__ B2,
                                                  const float* __restrict__ bias,
                                                  const float* __restrict__ aln,
                                                  float* __restrict__ C)
{
    const int N = CA, K = CS;
    __shared__ float As[16][68];
    __shared__ float Bs1[16][64];
    __shared__ float Bs2[16][64];
    int m0 = blockIdx.y * 64, n0 = blockIdx.x * 64;
    int tid = threadIdx.x, tx = tid & 15, ty = tid >> 4;
    float acc1[4][4] = {}, acc2[4][4] = {};
    for (int k0 = 0; k0 < K; k0 += 16) {
        int kk = tid & 15, mb = tid >> 4;
#pragma unroll
        for (int r = 0; r < 4; r++)
            As[kk][mb + r * 16] = A[(size_t)(m0 + mb + r * 16) * K + k0 + kk];
        int nn = tid & 63, kb = tid >> 6;
#pragma unroll
        for (int r = 0; r < 4; r++) {
            Bs1[kb + r * 4][nn] = B1[(size_t)(k0 + kb + r * 4) * N + n0 + nn];
            Bs2[kb + r * 4][nn] = B2[(size_t)(k0 + kb + r * 4) * N + n0 + nn];
        }
        __syncthreads();
#pragma unroll
        for (int k = 0; k < 16; k++) {
            float4 a4 = *(const float4*)&As[k][ty * 4];
            float4 c4 = *(const float4*)&Bs1[k][tx * 4];
            float4 d4 = *(const float4*)&Bs2[k][tx * 4];
            float av[4] = {a4.x, a4.y, a4.z, a4.w};
            float b1v[4] = {c4.x, c4.y, c4.z, c4.w};
            float b2v[4] = {d4.x, d4.y, d4.z, d4.w};
#pragma unroll
            for (int i2 = 0; i2 < 4; i2++)
#pragma unroll
                for (int j2 = 0; j2 < 4; j2++) {
                    acc1[i2][j2] += av[i2] * b1v[j2];
                    acc2[i2][j2] += av[i2] * b2v[j2];
                }
        }
        __syncthreads();
    }
#pragma unroll
    for (int i2 = 0; i2 < 4; i2++) {
        int m = m0 + ty * 4 + i2;
#pragma unroll
        for (int j2 = 0; j2 < 4; j2++) {
            int n = n0 + tx * 4 + j2;
            float gsig = 1.f / (1.f + __expf(-(acc1[i2][j2] + bias[n])));
            C[(size_t)m * N + n] = gsig * aln[(size_t)m * N + n] + acc2[i2][j2];
        }
    }
}

/* ---------------- pair bias: LN(z,128) @ Wb + beta -> bias[b,h,i,j] ----
   block = 1024 thr = 32 warps; warp w handles j = jt*32+w for fixed (b,i).
   16-value butterfly reduction: 16 SHFL/thread (was 80). */
__global__ __launch_bounds__(1024) void pairbias_kernel(const float* __restrict__ z,
                                                        const float* __restrict__ beta,
                                                        const float* __restrict__ lnw,
                                                        const float* __restrict__ lnb,
                                                        const float* __restrict__ Wb,
                                                        float* __restrict__ S)
{
    __shared__ float sWbT[16][128];
    __shared__ float sw[128], sb[128];
    __shared__ float sbeta[512];
    __shared__ float stage[16][32];
    int b = blockIdx.z, i = blockIdx.y, jt = blockIdx.x;
    int tid = threadIdx.x;
    for (int idx = tid; idx < 2048; idx += 1024) {
        int c = idx >> 4, h = idx & 15;           /* Wb row-major [128][16] */
        sWbT[h][c] = Wb[idx];
    }
    if (tid < 128) { sw[tid] = lnw[tid]; sb[tid] = lnb[tid]; }
    if (tid < 512) {
        size_t bo = ((size_t)(b * II + i) * II + jt * 32) * HH;
        sbeta[tid] = beta[bo + tid];              /* [j within tile][h], coalesced */
    }
    __syncthreads();
    int w = tid >> 5, lane = tid & 31;
    int j = jt * 32 + w;
    const float4 z4 = *(const float4*)(z + ((size_t)(b * II + i) * II + j) * CZ + lane * 4);
    float s  = z4.x + z4.y + z4.z + z4.w;
    float ss = z4.x * z4.x + z4.y * z4.y + z4.z * z4.z + z4.w * z4.w;
#pragma unroll
    for (int off = 16; off; off >>= 1) {
        s  += __shfl_xor_sync(0xffffffffu, s,  off);
        ss += __shfl_xor_sync(0xffffffffu, ss, off);
    }
    float mean = s * (1.f / CZ);
    float var  = ss * (1.f / CZ) - mean * mean;
    float inv  = rsqrtf(var + EPSV);
    int c0 = lane * 4;
    float y0 = (z4.x - mean) * inv * sw[c0 + 0] + sb[c0 + 0];
    float y1 = (z4.y - mean) * inv * sw[c0 + 1] + sb[c0 + 1];
    float y2 = (z4.z - mean) * inv * sw[c0 + 2] + sb[c0 + 2];
    float y3 = (z4.w - mean) * inv * sw[c0 + 3] + sb[c0 + 3];
    float acc[16];
#pragma unroll
    for (int h = 0; h < 16; h++) {
        float4 wv = *(const float4*)&sWbT[h][c0];
        acc[h] = y0 * wv.x + y1 * wv.y + y2 * wv.z + y3 * wv.w;
    }
    /* butterfly: sum each of 16 values over 32 lanes; result for h=(lane>>1)&15
       lands on every lane pair; even lane writes. */
    const unsigned FM = 0xffffffffu;
    bool b4 = (lane & 16) != 0;
    float t8[8];
#pragma unroll
    for (int h = 0; h < 8; h++) {
        float keep = b4 ? acc[h + 8] : acc[h];
        float send = b4 ? acc[h] : acc[h + 8];
        t8[h] = keep + __shfl_xor_sync(FM, send, 16);
    }
    bool b3 = (lane & 8) != 0;
    float t4[4];
#pragma unroll
    for (int h = 0; h < 4; h++) {
        float keep = b3 ? t8[h + 4] : t8[h];
        float send = b3 ? t8[h] : t8[h + 4];
        t4[h] = keep + __shfl_xor_sync(FM, send, 8);
    }
    bool b2 = (lane & 4) != 0;
    float t2[2];
#pragma unroll
    for (int h = 0; h < 2; h++) {
        float keep = b2 ? t4[h + 2] : t4[h];
        float send = b2 ? t4[h] : t4[h + 2];
        t2[h] = keep + __shfl_xor_sync(FM, send, 4);
    }
    bool b1 = (lane & 2) != 0;
    float keep1 = b1 ? t2[1] : t2[0];
    float send1 = b1 ? t2[0] : t2[1];
    float t1 = keep1 + __shfl_xor_sync(FM, send1, 2);
    t1 += __shfl_xor_sync(FM, t1, 1);
    if ((lane & 1) == 0) stage[(lane >> 1) & 15][w] = t1;
    __syncthreads();
    if (tid < 512) {                              /* coalesced j-contiguous write */
        int h = tid >> 5, jj = tid & 31;
        S[((size_t)(b * HH + h) * II + i) * II + jt * 32 + jj] =
            stage[h][jj] + sbeta[jj * HH + h];
    }
}

/* ---------------- fused flash attention ----------------
   per block: (b, h, 64 i-rows). QK^T + bias, online softmax over j,
   PV accumulate, gate with g, write o. */
__global__ __launch_bounds__(256) void flash_kernel(const float* __restrict__ qkvg,
                                                    const float* __restrict__ bias,
                                                    float* __restrict__ O)
{
    __shared__ float Qs[DD][68];    /* [d][i] */
    __shared__ float Ks[DD][68];    /* [d][j] */
    __shared__ float Vs[64][52];    /* [j][d] */
    __shared__ float sP[64][68];    /* [i][j] */
    __shared__ float sm[64], sl[64], srs[64];
    int b = blockIdx.z, h = blockIdx.y, i0 = blockIdx.x * 64;
    int tid = threadIdx.x, tx = tid & 15, ty = tid >> 4;

    /* load Q tile (transposed scatter) */
#pragma unroll
    for (int e = 0; e < 3; e++) {
        int idx = tid + e * 256;
        int row = idx / 12, c4 = idx % 12;
        float4 qv = *(const float4*)&qkvg[(size_t)(b * II + i0 + row) * QS + h * DD + c4 * 4];
        Qs[c4 * 4 + 0][row] = qv.x;
        Qs[c4 * 4 + 1][row] = qv.y;
        Qs[c4 * 4 + 2][row] = qv.z;
        Qs[c4 * 4 + 3][row] = qv.w;
    }
    if (tid < 64) { sm[tid] = -1e30f; sl[tid] = 0.f; }

    float oacc[4][3] = {};
    const float kscale = 0.14433756729740643f;    /* 1/sqrt(48) */
    const float* bb = bias + ((size_t)((b * HH + h) * II + i0)) * II;

    for (int j0 = 0; j0 < II; j0 += 64) {
        __syncthreads();    /* Ks/Vs/sP safe to overwrite */
#pragma unroll
        for (int e = 0; e < 3; e++) {
            int idx = tid + e * 256;
            int row = idx / 12, c4 = idx % 12;
            float4 kv = *(const float4*)&qkvg[(size_t)(b * II + j0 + row) * QS + HC + h * DD + c4 * 4];
            Ks[c4 * 4 + 0][row] = kv.x;
            Ks[c4 * 4 + 1][row] = kv.y;
            Ks[c4 * 4 + 2][row] = kv.z;
            Ks[c4 * 4 + 3][row] = kv.w;
            float4 vv = *(const float4*)&qkvg[(size_t)(b * II + j0 + row) * QS + 2 * HC + h * DD + c4 * 4];
            *(float4*)&Vs[row][c4 * 4] = vv;
        }
        __syncthreads();

        /* QK^T: thread = 4 i x 4 j */
        float s[4][4] = {};
#pragma unroll
        for (int d = 0; d < DD; d++) {
            float4 qa = *(const float4*)&Qs[d][ty * 4];
            float4 kb = *(const float4*)&Ks[d][tx * 4];
            float qv[4] = {qa.x, qa.y, qa.z, qa.w};
            float kv[4] = {kb.x, kb.y, kb.z, kb.w};
#pragma unroll
            for (int i2 = 0; i2 < 4; i2++)
#pragma unroll
                for (int j2 = 0; j2 < 4; j2++)
                    s[i2][j2] += qv[i2] * kv[j2];
        }
        const unsigned FM = 0xffffffffu;
#pragma unroll
        for (int i2 = 0; i2 < 4; i2++) {
            int row = ty * 4 + i2;
            float4 bv = *(const float4*)&bb[(size_t)row * II + j0 + tx * 4];
            s[i2][0] = s[i2][0] * kscale + bv.x;
            s[i2][1] = s[i2][1] * kscale + bv.y;
            s[i2][2] = s[i2][2] * kscale + bv.z;
            s[i2][3] = s[i2][3] * kscale + bv.w;
            /* row max across the 16 tx lanes */
            float mloc = fmaxf(fmaxf(s[i2][0], s[i2][1]), fmaxf(s[i2][2], s[i2][3]));
#pragma unroll
            for (int off = 8; off; off >>= 1)
                mloc = fmaxf(mloc, __shfl_xor_sync(FM, mloc, off));
            float m_old = sm[row];
            float m_new = fmaxf(m_old, mloc);
            float rsum = 0.f;
#pragma unroll
            for (int j2 = 0; j2 < 4; j2++) {
                float p = __expf(s[i2][j2] - m_new);
                s[i2][j2] = p;
                rsum += p;
            }
#pragma unroll
            for (int off = 8; off; off >>= 1)
                rsum += __shfl_xor_sync(FM, rsum, off);
            *(float4*)&sP[row][tx * 4] = make_float4(s[i2][0], s[i2][1], s[i2][2], s[i2][3]);
            if (tx == 0) {
                float f = __expf(m_old - m_new);
                srs[row] = f;
                sl[row] = sl[row] * f + rsum;
                sm[row] = m_new;
            }
        }
        __syncthreads();

        /* PV: thread = 4 i-rows x 3 d-cols */
#pragma unroll
        for (int i2 = 0; i2 < 4; i2++) {
            float f = srs[ty * 4 + i2];
            oacc[i2][0] *= f; oacc[i2][1] *= f; oacc[i2][2] *= f;
        }
#pragma unroll 4
        for (int jk = 0; jk < 64; jk++) {
            float v0 = Vs[jk][tx * 3 + 0];
            float v1 = Vs[jk][tx * 3 + 1];
            float v2 = Vs[jk][tx * 3 + 2];
#pragma unroll
            for (int i2 = 0; i2 < 4; i2++) {
                float p = sP[ty * 4 + i2][jk];
                oacc[i2][0] += p * v0;
                oacc[i2][1] += p * v1;
                oacc[i2][2] += p * v2;
            }
        }
    }
    __syncthreads();
#pragma unroll
    for (int i2 = 0; i2 < 4; i2++) {
        int row = ty * 4 + i2;
        float inv = 1.f / sl[row];
#pragma unroll
        for (int t = 0; t < 3; t++) {
            int d = tx * 3 + t;
            size_t gi = (size_t)(b * II + i0 + row) * QS + 3 * HC + h * DD + d;
            O[(size_t)(b * II + i0 + row) * HC + h * DD + d] = oacc[i2][t] * inv * qkvg[gi];
        }
    }
}

/* ---------------- host launcher ---------------- */
extern "C" void kernel_launch(void* const* d_in, const int* in_sizes, int n_in,
                              void* d_out, int out_size)
{
    (void)in_sizes; (void)n_in; (void)out_size;
    const float* a_i  = (const float*)d_in[0];
    const float* s_i  = (const float*)d_in[1];
    const float* z_ij = (const float*)d_in[2];
    const float* beta = (const float*)d_in[3];
    const float* lnsw = (const float*)d_in[4];
    const float* lnsb = (const float*)d_in[5];
    const float* Ws   = (const float*)d_in[6];
    const float* bs   = (const float*)d_in[7];
    const float* Wnb  = (const float*)d_in[8];
    const float* Wq   = (const float*)d_in[9];
    const float* bq   = (const float*)d_in[10];
    const float* Wk   = (const float*)d_in[11];
    const float* Wv   = (const float*)d_in[12];
    const float* lnbw = (const float*)d_in[13];
    const float* lnbb = (const float*)d_in[14];
    const float* Wb   = (const float*)d_in[15];
    const float* Wg   = (const float*)d_in[16];
    const float* Wo   = (const float*)d_in[17];
    const float* Wso  = (const float*)d_in[18];
    const float* bso  = (const float*)d_in[19];
    float* out = (float*)d_out;

    float *aln, *sln, *a, *wpk, *qkvg, *gate2, *o, *biasb;
    cudaGetSymbolAddress((void**)&aln,   g_aln);
    cudaGetSymbolAddress((void**)&sln,   g_sln);
    cudaGetSymbolAddress((void**)&a,     g_a);
    cudaGetSymbolAddress((void**)&wpk,   g_Wqkvg);
    cudaGetSymbolAddress((void**)&qkvg,  g_qkvg);
    cudaGetSymbolAddress((void**)&gate2, g_gate2);
    cudaGetSymbolAddress((void**)&o,     g_o);
    cudaGetSymbolAddress((void**)&biasb, g_bias);

    /* weight packing */
    pack_w<<<(CA * HC / 4) / 256, 256>>>(Wq, Wk, Wv, Wg, wpk);

    /* LayerNorms */
    ln_kernel<CA, false><<<MM, 256>>>(a_i, nullptr, nullptr, aln);
    ln_kernel<CS, true ><<<MM, 256>>>(s_i, lnsw, lnsb, sln);

    /* adaln: a = sigmoid(sln@Ws + bs) * aln + sln@Wnb */
    adaln_gemm<<<dim3(CA / 64, MM / 64), 256>>>(sln, Ws, Wnb, bs, aln, a);

    /* fused q|k|v|g projection GEMM: [1536,768] @ [768,3072] */
    gemm_big<5><<<dim3(QS / 128, MM / 128), 256>>>(a, wpk, qkvg, bq, nullptr, MM, QS, CA);

    /* output gate from RAW s_i: sigmoid(s_i@Ws_out + bs_out) */
    gemm_big<3><<<dim3(CA / 128, MM / 128), 256>>>(s_i, Wso, gate2, bso, nullptr, MM, CA, CS);

    /* pair bias -> bias[b,h,i,j] */
    pairbias_kernel<<<dim3(II / 32, II, BB), 1024>>>(z_ij, beta, lnbw, lnbb, Wb, biasb);

    /* fused attention: softmax_j(q.k/sqrt(d)+bias) @ v * g -> o */
    flash_kernel<<<dim3(II / 64, HH, BB), 256>>>(qkvg, biasb, o);

    /* out = gate2 * (o @ Wo) */
    gemm_big<4><<<dim3(CA / 128, MM / 128), 256>>>(o, Wo, out, nullptr, gate2, MM, CA, HC);
}